// round 8
// baseline (speedup 1.0000x reference)
#include <cuda_runtime.h>
#include <cuda_fp16.h>
#include <cstdint>

#define D_MODEL 1024
#define NE 64
#define NN 128
#define BK 64               // fp32 K per chunk (HMMA path)
#define NCH 16
#define H_CTAS 152
#define H_ROWS (H_CTAS * 128)   // 19456 rows via HMMA
#define F_TILE 32
#define CSTRIDE 132
#define FSTR 34             // FFMA A-smem stride (floats)
#define SMEM_BYTES 98304    // 96KB dynamic -> 2 CTAs/SM

// HMMA weights: pre-split fp16, pre-swizzled [split][chunk] 16KB images
__device__ __align__(128) unsigned char g_Bf[2 * NCH * 16384];
// FFMA weights: fp32 k-major [k][128]
__device__ __align__(16) float g_Wt[D_MODEL * NN];

#define SWZB(r, c) ((r) * 256 + ((c) ^ (((r) & 7) << 4)))

__device__ __forceinline__ uint32_t smem_u32(const void* p) {
    uint32_t a;
    asm("{ .reg .u64 t; cvta.to.shared.u64 t, %1; cvt.u32.u64 %0, t; }" : "=r"(a) : "l"(p));
    return a;
}
#define CP16(dst, src) asm volatile("cp.async.ca.shared.global [%0], [%1], 16;" :: "r"(dst), "l"(src))
#define CP_COMMIT()    asm volatile("cp.async.commit_group;")
#define CP_WAIT0()     asm volatile("cp.async.wait_group 0;")

#define LDSM4(r, p) \
    asm volatile("ldmatrix.sync.aligned.m8n8.x4.shared.b16 {%0,%1,%2,%3}, [%4];" \
                 : "=r"((r)[0]), "=r"((r)[1]), "=r"((r)[2]), "=r"((r)[3]) : "r"(p))
#define LDSM4T(r, p) \
    asm volatile("ldmatrix.sync.aligned.m8n8.x4.trans.shared.b16 {%0,%1,%2,%3}, [%4];" \
                 : "=r"((r)[0]), "=r"((r)[1]), "=r"((r)[2]), "=r"((r)[3]) : "r"(p))
#define MMA16816(d, a, b0, b1) \
    asm volatile("mma.sync.aligned.m16n8k16.row.col.f32.f16.f16.f32 " \
                 "{%0,%1,%2,%3}, {%4,%5,%6,%7}, {%8,%9}, {%0,%1,%2,%3};" \
                 : "+f"((d)[0]), "+f"((d)[1]), "+f"((d)[2]), "+f"((d)[3]) \
                 : "r"((a)[0]), "r"((a)[1]), "r"((a)[2]), "r"((a)[3]), "r"(b0), "r"(b1))

// ============================================================
// Prep kernels
// ============================================================
__global__ void prep_w(const float* __restrict__ Wr, const float* __restrict__ Wn) {
    int idx = blockIdx.x * blockDim.x + threadIdx.x;
    int k = idx >> 6;
    int n = (idx & 63) * 2;
    float x = (n < NE) ? Wr[n * D_MODEL + k] : Wn[(n - NE) * D_MODEL + k];
    float y = (n + 1 < NE) ? Wr[(n + 1) * D_MODEL + k] : Wn[(n + 1 - NE) * D_MODEL + k];
    __half2 h0 = __floats2half2_rn(x, y);
    float2 f0 = __half22float2(h0);
    __half2 h1 = __floats2half2_rn(x - f0.x, y - f0.y);
    int c = k >> 6, kr = k & 63;
    uint32_t off = SWZB(kr, n * 2);
    *(uint32_t*)(g_Bf + ((size_t)c << 14) + off) = reinterpret_cast<uint32_t&>(h0);
    *(uint32_t*)(g_Bf + (((size_t)(NCH + c)) << 14) + off) = reinterpret_cast<uint32_t&>(h1);
    // fp32 k-major for FFMA path
    g_Wt[k * NN + n]     = x;
    g_Wt[k * NN + n + 1] = y;
}

// ============================================================
// Shared router epilogue: C[ntok][CSTRIDE] in smem -> out
// ============================================================
__device__ __forceinline__ void router_ep(const float* C, const float* bias,
                                          const float* __restrict__ noise,
                                          float* __restrict__ out,
                                          int tok0, int ntok, int M, int write_idx, int tid) {
    if (tid >= ntok) return;
    const int token = tok0 + tid;
    const float* crow = C + tid * CSTRIDE;
    const float* nrow = noise + (size_t)token * NE;
    float nz[NE];
#pragma unroll
    for (int q = 0; q < NE / 4; q++) *(float4*)(nz + q * 4) = *(const float4*)(nrow + q * 4);

    float v1 = -1e30f, v2 = -1e30f;
    int i1 = 0, i2 = 0;
#pragma unroll 8
    for (int e = 0; e < NE; e++) {
        float rl  = crow[e] + bias[e];
        float nlg = crow[NE + e] + bias[NE + e];
        float sp  = fmaxf(nlg, 0.f) + log1pf(expf(-fabsf(nlg)));
        float z   = rl + nz[e] * sp;
        if (z > v1)      { v2 = v1; i2 = i1; v1 = z; i1 = e; }
        else if (z > v2) { v2 = z; i2 = e; }
    }
    float ex  = expf(v2 - v1);
    float inv = 1.f / (1.f + ex);
    float p1 = inv, p2 = ex * inv;

    float* orow = out + (size_t)token * NE;
    float4 zf = make_float4(0.f, 0.f, 0.f, 0.f);
#pragma unroll
    for (int q = 0; q < NE / 4; q++) *(float4*)(orow + q * 4) = zf;
    orow[i1] = p1;
    orow[i2] = p2;
    if (write_idx) {
        float2 iv = make_float2((float)i1, (float)i2);
        *(float2*)(out + (size_t)M * NE + (size_t)token * 2) = iv;
    }
}

__device__ __forceinline__ void split_pack8(float4 a, float4 b, uint4& s0, uint4& s1) {
    __half2 p0 = __floats2half2_rn(a.x, a.y);
    __half2 p1 = __floats2half2_rn(a.z, a.w);
    __half2 p2 = __floats2half2_rn(b.x, b.y);
    __half2 p3 = __floats2half2_rn(b.z, b.w);
    float2 f0 = __half22float2(p0), f1 = __half22float2(p1);
    float2 f2 = __half22float2(p2), f3 = __half22float2(p3);
    __half2 q0 = __floats2half2_rn(a.x - f0.x, a.y - f0.y);
    __half2 q1 = __floats2half2_rn(a.z - f1.x, a.w - f1.y);
    __half2 q2 = __floats2half2_rn(b.x - f2.x, b.y - f2.y);
    __half2 q3 = __floats2half2_rn(b.z - f3.x, b.w - f3.y);
    s0.x = reinterpret_cast<uint32_t&>(p0); s0.y = reinterpret_cast<uint32_t&>(p1);
    s0.z = reinterpret_cast<uint32_t&>(p2); s0.w = reinterpret_cast<uint32_t&>(p3);
    s1.x = reinterpret_cast<uint32_t&>(q0); s1.y = reinterpret_cast<uint32_t&>(q1);
    s1.z = reinterpret_cast<uint32_t&>(q2); s1.w = reinterpret_cast<uint32_t&>(q3);
}

// ============================================================
// Hybrid kernel: bids [0,152) = HMMA path (128 rows each, 2x64 sub-tiles)
//                bids [152,..) = FFMA path (32 rows each, f32x2)
// ============================================================
__global__ void __launch_bounds__(256, 2)
moe_hybrid(const float* __restrict__ A, const float* __restrict__ noise,
           const float* __restrict__ br, const float* __restrict__ bn,
           float* __restrict__ out, int M, int write_idx) {
    extern __shared__ __align__(128) unsigned char smem[];
    __shared__ float bias[NN];
    const uint32_t sb = smem_u32(smem);
    const int tid = threadIdx.x;
    const int bid = blockIdx.x;

    if (tid < NN) bias[tid] = (tid < NE) ? br[tid] : bn[tid - NE];
    __syncthreads();

    if (bid < H_CTAS) {
        // ================= HMMA path: 64-row sub-tiles, BK=64 =================
        const int w = tid >> 5, l = tid & 31;
        const int wm = (w & 3) * 16;          // 4 row groups x 16
        const int n0 = (w >> 2) * 64;         // 2 col groups x 64

        const int l16 = l & 15;
        const uint32_t khalf16 = (uint32_t)((l >> 4) << 4);
        const uint32_t Ra  = (uint32_t)(wm + l16) * 128;
        const uint32_t rxa = ((uint32_t)((wm + l16) & 7)) << 4;
        const uint32_t Rb0 = (uint32_t)l16 * 256;
        const uint32_t rxb = ((uint32_t)(l16 & 7)) << 4;
        const uint32_t cbb = (uint32_t)(n0 * 2) + khalf16;

        const int arow = tid >> 2, aq = tid & 3;   // 64 rows, 16 floats each
        const uint32_t arow_rx = ((uint32_t)(arow & 7)) << 4;
        const uint32_t a_st_row = (uint32_t)arow * 128;

        for (int t = 0; t < 2; t++) {
            const int m0 = bid * 128 + t * 64;
            const float* aptr = A + (size_t)(m0 + arow) * D_MODEL + aq * 16;

            float acc[8][4];
#pragma unroll
            for (int j = 0; j < 8; j++)
#pragma unroll
                for (int q = 0; q < 4; q++) acc[j][q] = 0.f;

            float4 av[4];
            auto ldg_a = [&](int c) {
#pragma unroll
                for (int i = 0; i < 4; i++) av[i] = *(const float4*)(aptr + c * BK + i * 4);
            };
            auto cp_b = [&](int c, int buf) {
#pragma unroll
                for (int s = 0; s < 2; s++) {
                    const unsigned char* src = g_Bf + (((size_t)(s * NCH + c)) << 14);
                    uint32_t dst = sb + 32768 + buf * 32768 + s * 16384;
#pragma unroll
                    for (int j = 0; j < 4; j++) {
                        uint32_t o = (uint32_t)(tid + j * 256) * 16;
                        CP16(dst + o, src + o);
                    }
                }
                CP_COMMIT();
            };
            auto sts_a = [&](int buf) {
                unsigned char* b0 = smem + buf * 16384;
#pragma unroll
                for (int g = 0; g < 2; g++) {
                    uint4 s0, s1;
                    split_pack8(av[2 * g], av[2 * g + 1], s0, s1);
                    uint32_t phys = a_st_row + (((uint32_t)(aq * 32 + g * 16)) ^ arow_rx);
                    *(uint4*)(b0 + phys) = s0;
                    *(uint4*)(b0 + 8192 + phys) = s1;
                }
            };

            ldg_a(0);
            cp_b(0, 0);
            sts_a(0);
            CP_WAIT0();
            __syncthreads();

            for (int c = 0; c < NCH; c++) {
                int buf = c & 1;
                if (c + 1 < NCH) { ldg_a(c + 1); cp_b(c + 1, buf ^ 1); }

                uint32_t Ab = sb + buf * 16384;
                uint32_t Bb = sb + 32768 + buf * 32768;
#pragma unroll
                for (int ks = 0; ks < 4; ks++) {
                    uint32_t ca = ((uint32_t)(ks * 32) + khalf16) ^ rxa;
                    uint32_t a0f[4], a1f[4];
                    LDSM4(a0f, Ab + Ra + ca);
                    LDSM4(a1f, Ab + 8192 + Ra + ca);

                    uint32_t Rb = Rb0 + (uint32_t)ks * 4096;
                    uint32_t b0f[4][4], b1f[4][4];
#pragma unroll
                    for (int nt = 0; nt < 4; nt++) {
                        uint32_t cc = (cbb + (uint32_t)(nt * 32)) ^ rxb;
                        LDSM4T(b0f[nt], Bb + Rb + cc);
                        LDSM4T(b1f[nt], Bb + 16384 + Rb + cc);
                    }
#pragma unroll
                    for (int nt = 0; nt < 4; nt++) {
                        MMA16816(acc[2 * nt],     a0f, b0f[nt][0], b0f[nt][1]);
                        MMA16816(acc[2 * nt + 1], a0f, b0f[nt][2], b0f[nt][3]);
                    }
#pragma unroll
                    for (int nt = 0; nt < 4; nt++) {
                        MMA16816(acc[2 * nt],     a0f, b1f[nt][0], b1f[nt][1]);
                        MMA16816(acc[2 * nt + 1], a0f, b1f[nt][2], b1f[nt][3]);
                    }
#pragma unroll
                    for (int nt = 0; nt < 4; nt++) {
                        MMA16816(acc[2 * nt],     a1f, b0f[nt][0], b0f[nt][1]);
                        MMA16816(acc[2 * nt + 1], a1f, b0f[nt][2], b0f[nt][3]);
                    }
                }

                if (c + 1 < NCH) { sts_a(buf ^ 1); CP_WAIT0(); }
                __syncthreads();
            }

            // epilogue: C[64][CSTRIDE] @ smem 0
            float* C = (float*)smem;
            {
                int r0 = wm + (l >> 2);
                int cb = n0 + (l & 3) * 2;
#pragma unroll
                for (int j = 0; j < 8; j++) {
                    int cc = cb + j * 8;
                    *(float2*)(C + r0 * CSTRIDE + cc)       = *(float2*)&acc[j][0];
                    *(float2*)(C + (r0 + 8) * CSTRIDE + cc) = *(float2*)&acc[j][2];
                }
            }
            __syncthreads();
            router_ep(C, bias, noise, out, m0, 64, M, write_idx, tid);
            __syncthreads();   // protect C before next sub-tile reuses smem
        }
    } else {
        // ================= FFMA path: 32-row tile, f32x2, BK=32 =================
        const int j = bid - H_CTAS;
        const int f0 = H_ROWS + j * F_TILE;
        const int tr = tid >> 3;          // 0..31 : one row each
        const int tc = tid & 7;           // 8 col groups x 16 strided cols

        float* AsF = (float*)(smem + 20480);           // [2][32][FSTR]
        const uint32_t bB = sb + 32768;                // B: [2][32*128] f32

        const int ar = tid >> 3, ak4 = (tid & 7) * 4;  // A loader: 1 float4/thread
        const float* aptr = A + (size_t)(f0 + ar) * D_MODEL + ak4;

        unsigned long long acc[8];
#pragma unroll
        for (int p = 0; p < 8; p++) acc[p] = 0ull;

        float4 av;
        auto ldg_a = [&](int c) { av = *(const float4*)(aptr + c * 32); };
        auto cp_b = [&](int c, int buf) {
            const float* src = g_Wt + (size_t)c * 32 * NN;
            uint32_t dst = bB + buf * 16384;
#pragma unroll
            for (int q = 0; q < 4; q++) {
                uint32_t o = (uint32_t)(tid + q * 256) * 16;
                CP16(dst + o, (const unsigned char*)src + o);
            }
            CP_COMMIT();
        };
        auto sts_a = [&](int buf) {
            float* d = AsF + buf * (32 * FSTR);
            d[(ak4 + 0) * FSTR + ar] = av.x;
            d[(ak4 + 1) * FSTR + ar] = av.y;
            d[(ak4 + 2) * FSTR + ar] = av.z;
            d[(ak4 + 3) * FSTR + ar] = av.w;
        };

        ldg_a(0);
        cp_b(0, 0);
        sts_a(0);
        CP_WAIT0();
        __syncthreads();

        for (int c = 0; c < 32; c++) {
            int buf = c & 1;
            if (c + 1 < 32) { ldg_a(c + 1); cp_b(c + 1, buf ^ 1); }

            const float* Ak = AsF + buf * (32 * FSTR) + tr;
            uint32_t Bk = bB + buf * 16384 + tc * 16;
#pragma unroll 8
            for (int k = 0; k < 32; k++) {
                float a = Ak[k * FSTR];
                unsigned long long ad;
                asm("mov.b64 %0,{%1,%1};" : "=l"(ad) : "f"(a));
                unsigned long long bq[8];
#pragma unroll
                for (int q = 0; q < 4; q++) {
                    asm volatile("ld.shared.v2.b64 {%0,%1},[%2];"
                                 : "=l"(bq[2 * q]), "=l"(bq[2 * q + 1])
                                 : "r"(Bk + (uint32_t)k * 512 + (uint32_t)q * 128));
                }
#pragma unroll
                for (int p = 0; p < 8; p++)
                    asm("fma.rn.f32x2 %0,%1,%2,%0;" : "+l"(acc[p]) : "l"(ad), "l"(bq[p]));
            }

            if (c + 1 < 32) { sts_a(buf ^ 1); CP_WAIT0(); }
            __syncthreads();
        }

        // epilogue: C[32][CSTRIDE] @ smem 0
        float* C = (float*)smem;
#pragma unroll
        for (int q = 0; q < 4; q++) {
            *(float2*)(C + tr * CSTRIDE + tc * 4 + q * 32)     = *(float2*)&acc[2 * q];
            *(float2*)(C + tr * CSTRIDE + tc * 4 + q * 32 + 2) = *(float2*)&acc[2 * q + 1];
        }
        __syncthreads();
        router_ep(C, bias, noise, out, f0, F_TILE, M, write_idx, tid);
    }
}

// ============================================================
extern "C" void kernel_launch(void* const* d_in, const int* in_sizes, int n_in,
                              void* d_out, int out_size) {
    const float* mh    = (const float*)d_in[0];
    const float* noise = (const float*)d_in[1];
    const float* Wr    = (const float*)d_in[2];
    const float* br    = (const float*)d_in[3];
    const float* Wn    = (const float*)d_in[4];
    const float* bn    = (const float*)d_in[5];
    float* out = (float*)d_out;

    int M = in_sizes[0] / D_MODEL;   // 32768

    cudaFuncSetAttribute(moe_hybrid, cudaFuncAttributeMaxDynamicSharedMemorySize, SMEM_BYTES);

    prep_w<<<(D_MODEL * NN / 2) / 256, 256>>>(Wr, Wn);

    int f_ctas = (M - H_ROWS) / F_TILE;      // 416
    int write_idx = (out_size >= M * NE + M * 2) ? 1 : 0;
    moe_hybrid<<<H_CTAS + f_ctas, 256, SMEM_BYTES>>>(mh, noise, br, bn, out, M, write_idx);
}

// round 9
// speedup vs baseline: 2.5135x; 2.5135x over previous
#include <cuda_runtime.h>
#include <cuda_fp16.h>
#include <cstdint>

#define D_MODEL 1024
#define NE 64
#define NN 128
#define BM 64               // tokens per CTA
#define BK 64               // fp32 K per chunk
#define NCH 16
#define CSTRIDE 132
#define SMEM_BYTES 98304    // 96KB -> 2 CTAs/SM

// pre-split fp16 weights, pre-swizzled [split][chunk] 16KB images
__device__ __align__(128) unsigned char g_Bf[2 * NCH * 16384];

#define SWZB(r, c) ((r) * 256 + ((c) ^ (((r) & 7) << 4)))

__device__ __forceinline__ uint32_t smem_u32(const void* p) {
    uint32_t a;
    asm("{ .reg .u64 t; cvta.to.shared.u64 t, %1; cvt.u32.u64 %0, t; }" : "=r"(a) : "l"(p));
    return a;
}
#define CP16(dst, src) asm volatile("cp.async.ca.shared.global [%0], [%1], 16;" :: "r"(dst), "l"(src))
#define CP_COMMIT()    asm volatile("cp.async.commit_group;")
#define CP_WAIT0()     asm volatile("cp.async.wait_group 0;")

#define LDSM4(r, p) \
    asm volatile("ldmatrix.sync.aligned.m8n8.x4.shared.b16 {%0,%1,%2,%3}, [%4];" \
                 : "=r"((r)[0]), "=r"((r)[1]), "=r"((r)[2]), "=r"((r)[3]) : "r"(p))
#define LDSM4T(r, p) \
    asm volatile("ldmatrix.sync.aligned.m8n8.x4.trans.shared.b16 {%0,%1,%2,%3}, [%4];" \
                 : "=r"((r)[0]), "=r"((r)[1]), "=r"((r)[2]), "=r"((r)[3]) : "r"(p))
#define MMA16816(d, a, b0, b1) \
    asm volatile("mma.sync.aligned.m16n8k16.row.col.f32.f16.f16.f32 " \
                 "{%0,%1,%2,%3}, {%4,%5,%6,%7}, {%8,%9}, {%0,%1,%2,%3};" \
                 : "+f"((d)[0]), "+f"((d)[1]), "+f"((d)[2]), "+f"((d)[3]) \
                 : "r"((a)[0]), "r"((a)[1]), "r"((a)[2]), "r"((a)[3]), "r"(b0), "r"(b1))

// ============================================================
// Prep: fp16 2-split of W_route||W_noise into swizzled k-chunk images
// ============================================================
__global__ void prep_w(const float* __restrict__ Wr, const float* __restrict__ Wn) {
    int idx = blockIdx.x * blockDim.x + threadIdx.x;
    int k = idx >> 6;
    int n = (idx & 63) * 2;
    float x = (n < NE) ? Wr[n * D_MODEL + k] : Wn[(n - NE) * D_MODEL + k];
    float y = (n + 1 < NE) ? Wr[(n + 1) * D_MODEL + k] : Wn[(n + 1 - NE) * D_MODEL + k];
    __half2 h0 = __floats2half2_rn(x, y);
    float2 f0 = __half22float2(h0);
    __half2 h1 = __floats2half2_rn(x - f0.x, y - f0.y);
    int c = k >> 6, kr = k & 63;
    uint32_t off = SWZB(kr, n * 2);
    *(uint32_t*)(g_Bf + ((size_t)c << 14) + off) = reinterpret_cast<uint32_t&>(h0);
    *(uint32_t*)(g_Bf + (((size_t)(NCH + c)) << 14) + off) = reinterpret_cast<uint32_t&>(h1);
}

__device__ __forceinline__ void split_pack8(float4 a, float4 b, uint4& s0, uint4& s1) {
    __half2 p0 = __floats2half2_rn(a.x, a.y);
    __half2 p1 = __floats2half2_rn(a.z, a.w);
    __half2 p2 = __floats2half2_rn(b.x, b.y);
    __half2 p3 = __floats2half2_rn(b.z, b.w);
    float2 f0 = __half22float2(p0), f1 = __half22float2(p1);
    float2 f2 = __half22float2(p2), f3 = __half22float2(p3);
    __half2 q0 = __floats2half2_rn(a.x - f0.x, a.y - f0.y);
    __half2 q1 = __floats2half2_rn(a.z - f1.x, a.w - f1.y);
    __half2 q2 = __floats2half2_rn(b.x - f2.x, b.y - f2.y);
    __half2 q3 = __floats2half2_rn(b.z - f3.x, b.w - f3.y);
    s0.x = reinterpret_cast<uint32_t&>(p0); s0.y = reinterpret_cast<uint32_t&>(p1);
    s0.z = reinterpret_cast<uint32_t&>(p2); s0.w = reinterpret_cast<uint32_t&>(p3);
    s1.x = reinterpret_cast<uint32_t&>(q0); s1.y = reinterpret_cast<uint32_t&>(q1);
    s1.z = reinterpret_cast<uint32_t&>(q2); s1.w = reinterpret_cast<uint32_t&>(q3);
}

// ============================================================
// BM=64 split-fp16 HMMA GEMM + fused router epilogue. 2 CTAs/SM.
// smem: A [2buf][2split][8KB] @0 (32KB), B [2buf][2split][16KB] @32768 (64KB)
// ============================================================
__global__ void __launch_bounds__(256, 2)
moe_mma(const float* __restrict__ A, const float* __restrict__ noise,
        const float* __restrict__ br, const float* __restrict__ bn,
        float* __restrict__ out, int M, int write_idx) {
    extern __shared__ __align__(128) unsigned char smem[];
    __shared__ float bias[NN];
    const uint32_t sb = smem_u32(smem);
    const int tid = threadIdx.x;
    const int w = tid >> 5, l = tid & 31;
    const int m0 = blockIdx.x * BM;

    if (tid < NN) bias[tid] = (tid < NE) ? br[tid] : bn[tid - NE];

    const int wm = (w & 3) * 16;          // 4 row groups x 16 rows
    const int n0 = (w >> 2) * 64;         // 2 col groups x 64 cols

    const int l16 = l & 15;
    const uint32_t khalf16 = (uint32_t)((l >> 4) << 4);
    const uint32_t Ra  = (uint32_t)(wm + l16) * 128;
    const uint32_t rxa = ((uint32_t)((wm + l16) & 7)) << 4;
    const uint32_t Rb0 = (uint32_t)l16 * 256;
    const uint32_t rxb = ((uint32_t)(l16 & 7)) << 4;
    const uint32_t cbb = (uint32_t)(n0 * 2) + khalf16;

    // A loader: 64 rows, 4 threads/row, 16 floats each
    const int arow = tid >> 2, aq = tid & 3;
    const float* aptr = A + (size_t)(m0 + arow) * D_MODEL + aq * 16;
    const uint32_t arow_rx = ((uint32_t)(arow & 7)) << 4;
    const uint32_t a_st_row = (uint32_t)arow * 128;

    float acc[8][4];
#pragma unroll
    for (int j = 0; j < 8; j++)
#pragma unroll
        for (int q = 0; q < 4; q++) acc[j][q] = 0.f;

    float4 av[4];
    auto ldg_a = [&](int c) {
#pragma unroll
        for (int i = 0; i < 4; i++) av[i] = *(const float4*)(aptr + c * BK + i * 4);
    };
    auto cp_b = [&](int c, int buf) {
#pragma unroll
        for (int s = 0; s < 2; s++) {
            const unsigned char* src = g_Bf + (((size_t)(s * NCH + c)) << 14);
            uint32_t dst = sb + 32768 + buf * 32768 + s * 16384;
#pragma unroll
            for (int j = 0; j < 4; j++) {
                uint32_t o = (uint32_t)(tid + j * 256) * 16;
                CP16(dst + o, src + o);
            }
        }
        CP_COMMIT();
    };
    auto sts_a = [&](int buf) {
        unsigned char* b0 = smem + buf * 16384;
#pragma unroll
        for (int g = 0; g < 2; g++) {
            uint4 s0, s1;
            split_pack8(av[2 * g], av[2 * g + 1], s0, s1);
            uint32_t phys = a_st_row + (((uint32_t)(aq * 32 + g * 16)) ^ arow_rx);
            *(uint4*)(b0 + phys) = s0;
            *(uint4*)(b0 + 8192 + phys) = s1;
        }
    };

    ldg_a(0);
    cp_b(0, 0);
    sts_a(0);
    CP_WAIT0();
    __syncthreads();

    for (int c = 0; c < NCH; c++) {
        int buf = c & 1;
        if (c + 1 < NCH) { ldg_a(c + 1); cp_b(c + 1, buf ^ 1); }

        uint32_t Ab = sb + buf * 16384;
        uint32_t Bb = sb + 32768 + buf * 32768;
#pragma unroll
        for (int ks = 0; ks < 4; ks++) {
            uint32_t ca = ((uint32_t)(ks * 32) + khalf16) ^ rxa;
            uint32_t a0f[4], a1f[4];
            LDSM4(a0f, Ab + Ra + ca);
            LDSM4(a1f, Ab + 8192 + Ra + ca);

            uint32_t Rb = Rb0 + (uint32_t)ks * 4096;
            uint32_t b0f[4][4], b1f[4][4];
#pragma unroll
            for (int nt = 0; nt < 4; nt++) {
                uint32_t cc = (cbb + (uint32_t)(nt * 32)) ^ rxb;
                LDSM4T(b0f[nt], Bb + Rb + cc);
                LDSM4T(b1f[nt], Bb + 16384 + Rb + cc);
            }
#pragma unroll
            for (int nt = 0; nt < 4; nt++) {
                MMA16816(acc[2 * nt],     a0f, b0f[nt][0], b0f[nt][1]);
                MMA16816(acc[2 * nt + 1], a0f, b0f[nt][2], b0f[nt][3]);
            }
#pragma unroll
            for (int nt = 0; nt < 4; nt++) {
                MMA16816(acc[2 * nt],     a0f, b1f[nt][0], b1f[nt][1]);
                MMA16816(acc[2 * nt + 1], a0f, b1f[nt][2], b1f[nt][3]);
            }
#pragma unroll
            for (int nt = 0; nt < 4; nt++) {
                MMA16816(acc[2 * nt],     a1f, b0f[nt][0], b0f[nt][1]);
                MMA16816(acc[2 * nt + 1], a1f, b0f[nt][2], b0f[nt][3]);
            }
        }

        if (c + 1 < NCH) { sts_a(buf ^ 1); CP_WAIT0(); }
        __syncthreads();
    }

    // ---- epilogue: accs -> SMEM C [64][CSTRIDE] ----
    float* C = (float*)smem;
    {
        int r0 = wm + (l >> 2);
        int cb = n0 + (l & 3) * 2;
#pragma unroll
        for (int j = 0; j < 8; j++) {
            int cc = cb + j * 8;
            *(float2*)(C + r0 * CSTRIDE + cc)       = *(float2*)&acc[j][0];
            *(float2*)(C + (r0 + 8) * CSTRIDE + cc) = *(float2*)&acc[j][2];
        }
    }
    __syncthreads();

    if (tid < BM) {
        const int token = m0 + tid;
        const float* crow = C + tid * CSTRIDE;
        const float* nrow = noise + (size_t)token * NE;
        float nz[NE];
#pragma unroll
        for (int q = 0; q < NE / 4; q++) *(float4*)(nz + q * 4) = *(const float4*)(nrow + q * 4);

        float v1 = -1e30f, v2 = -1e30f;
        int i1 = 0, i2 = 0;
#pragma unroll 8
        for (int e = 0; e < NE; e++) {
            float rl  = crow[e] + bias[e];
            float nlg = crow[NE + e] + bias[NE + e];
            float sp  = fmaxf(nlg, 0.f) + log1pf(expf(-fabsf(nlg)));
            float z   = rl + nz[e] * sp;
            if (z > v1)      { v2 = v1; i2 = i1; v1 = z; i1 = e; }
            else if (z > v2) { v2 = z; i2 = e; }
        }

        float ex  = expf(v2 - v1);
        float inv = 1.f / (1.f + ex);
        float p1 = inv, p2 = ex * inv;

        float* orow = out + (size_t)token * NE;
        float4 zf = make_float4(0.f, 0.f, 0.f, 0.f);
#pragma unroll
        for (int q = 0; q < NE / 4; q++) *(float4*)(orow + q * 4) = zf;
        orow[i1] = p1;
        orow[i2] = p2;

        if (write_idx) {
            float2 iv = make_float2((float)i1, (float)i2);
            *(float2*)(out + (size_t)M * NE + (size_t)token * 2) = iv;
        }
    }
}

// ============================================================
extern "C" void kernel_launch(void* const* d_in, const int* in_sizes, int n_in,
                              void* d_out, int out_size) {
    const float* mh    = (const float*)d_in[0];
    const float* noise = (const float*)d_in[1];
    const float* Wr    = (const float*)d_in[2];
    const float* br    = (const float*)d_in[3];
    const float* Wn    = (const float*)d_in[4];
    const float* bn    = (const float*)d_in[5];
    float* out = (float*)d_out;

    int M = in_sizes[0] / D_MODEL;   // 32768

    cudaFuncSetAttribute(moe_mma, cudaFuncAttributeMaxDynamicSharedMemorySize, SMEM_BYTES);

    prep_w<<<(D_MODEL * NN / 2) / 256, 256>>>(Wr, Wn);

    int write_idx = (out_size >= M * NE + M * 2) ? 1 : 0;
    moe_mma<<<M / BM, 256, SMEM_BYTES>>>(mh, noise, br, bn, out, M, write_idx);
}